// round 3
// baseline (speedup 1.0000x reference)
#include <cuda_runtime.h>

// Problem constants (match reference)
#define N_SRC   20000
#define N_DST   20000
#define N_NODES 40000
#define E_TOT   320000
#define NHEAD   8
#define HDIM    16
#define FDIM    128
#define TEM     0.7f
#define NEG_SLOPE 0.2f

// Scratch (device globals; no allocations allowed)
__device__ float g_z[N_NODES * FDIM];        // 20.5 MB, L2-resident
__device__ float g_el[N_NODES * NHEAD];
__device__ float g_er[N_NODES * NHEAD];
__device__ int   g_counts[N_DST];
__device__ int   g_rowptr[N_DST + 1];
__device__ int   g_cursor[N_DST];
__device__ int   g_packed[E_TOT];            // src | (neg_flag << 31)
__device__ unsigned char g_flags[E_TOT];
__device__ float g_hneg[N_DST * HDIM];

// ---------------------------------------------------------------------------
// 1) z = feat @ fc_w  (40000x128 @ 128x128), fused el/er epilogue.
//    Block (32,8): each warp computes one output row (128 cols, 4/lane).
// ---------------------------------------------------------------------------
__global__ void gemm_el_er_kernel(const float* __restrict__ feat,
                                  const float* __restrict__ fc_w,
                                  const float* __restrict__ attn_l,
                                  const float* __restrict__ attn_r) {
    __shared__ float sA[8][FDIM];
    __shared__ float sB[32][FDIM];
    const int tx = threadIdx.x, ty = threadIdx.y;
    const int tid = ty * 32 + tx;
    const int row0 = blockIdx.x * 8;

    {   // load A tile 8x128 (one float4 per thread, coalesced)
        int r = tid >> 5, c4 = tid & 31;
        float4 v = *(const float4*)(feat + (size_t)(row0 + r) * FDIM + c4 * 4);
        *(float4*)(&sA[r][c4 * 4]) = v;
    }

    float4 acc = make_float4(0.f, 0.f, 0.f, 0.f);
    for (int kc = 0; kc < 4; kc++) {
        __syncthreads();
        // load B chunk 32x128 (4 float4 per thread)
        #pragma unroll
        for (int kk = 0; kk < 4; kk++) {
            int idx = kk * 256 + tid;
            int k = idx >> 5, c4 = idx & 31;
            float4 v = *(const float4*)(fc_w + (size_t)(kc * 32 + k) * FDIM + c4 * 4);
            *(float4*)(&sB[k][c4 * 4]) = v;
        }
        __syncthreads();
        #pragma unroll
        for (int k = 0; k < 32; k++) {
            float a = sA[ty][kc * 32 + k];
            float4 b = *(const float4*)(&sB[k][tx * 4]);
            acc.x = fmaf(a, b.x, acc.x);
            acc.y = fmaf(a, b.y, acc.y);
            acc.z = fmaf(a, b.z, acc.z);
            acc.w = fmaf(a, b.w, acc.w);
        }
    }

    const int row = row0 + ty;
    *(float4*)(g_z + (size_t)row * FDIM + tx * 4) = acc;

    // fused el/er: head h = tx/4, dims d0..d0+3, d0 = (tx%4)*4
    const int h = tx >> 2, d0 = (tx & 3) * 4;
    const float* al = attn_l + h * HDIM + d0;
    const float* ar = attn_r + h * HDIM + d0;
    float elp = acc.x * al[0] + acc.y * al[1] + acc.z * al[2] + acc.w * al[3];
    float erp = acc.x * ar[0] + acc.y * ar[1] + acc.z * ar[2] + acc.w * ar[3];
    elp += __shfl_xor_sync(0xffffffffu, elp, 1);
    elp += __shfl_xor_sync(0xffffffffu, elp, 2);
    erp += __shfl_xor_sync(0xffffffffu, erp, 1);
    erp += __shfl_xor_sync(0xffffffffu, erp, 2);
    if ((tx & 3) == 0) {
        g_el[row * NHEAD + h] = elp;
        g_er[row * NHEAD + h] = erp;
    }
}

// ---------------------------------------------------------------------------
// 2) CSR build over dst nodes
// ---------------------------------------------------------------------------
__global__ void zero_kernel() {
    int i = blockIdx.x * blockDim.x + threadIdx.x;
    if (i < N_DST) g_counts[i] = 0;
    if (i < E_TOT) g_flags[i] = 0;
}

__global__ void flags_kernel(const int* __restrict__ neg_idx, int e_neg) {
    int i = blockIdx.x * blockDim.x + threadIdx.x;
    if (i < e_neg) g_flags[neg_idx[i]] = 1;
}

__global__ void hist_kernel(const int* __restrict__ edge_dst) {
    int i = blockIdx.x * blockDim.x + threadIdx.x;
    if (i < E_TOT) atomicAdd(&g_counts[edge_dst[i] - N_SRC], 1);
}

__global__ void scan_kernel() {
    __shared__ int sh[1024];
    __shared__ int carry_s;
    const int tid = threadIdx.x;
    if (tid == 0) carry_s = 0;
    __syncthreads();
    for (int base = 0; base < N_DST; base += 1024) {
        int i = base + tid;
        int v = (i < N_DST) ? g_counts[i] : 0;
        sh[tid] = v;
        __syncthreads();
        for (int off = 1; off < 1024; off <<= 1) {
            int t = (tid >= off) ? sh[tid - off] : 0;
            __syncthreads();
            sh[tid] += t;
            __syncthreads();
        }
        int incl = sh[tid];
        int excl = incl - v + carry_s;
        if (i < N_DST) { g_rowptr[i] = excl; g_cursor[i] = excl; }
        int last = sh[1023];
        __syncthreads();
        if (tid == 0) carry_s += last;
        __syncthreads();
    }
    if (tid == 0) g_rowptr[N_DST] = carry_s;
}

__global__ void scatter_kernel(const int* __restrict__ edge_src,
                               const int* __restrict__ edge_dst) {
    int i = blockIdx.x * blockDim.x + threadIdx.x;
    if (i >= E_TOT) return;
    int d = edge_dst[i] - N_SRC;
    int pos = atomicAdd(&g_cursor[d], 1);
    g_packed[pos] = edge_src[i] | ((int)g_flags[i] << 31);
}

// ---------------------------------------------------------------------------
// 3) Aggregation: one warp per dst node, online softmax, fused pos+neg.
//    lane l holds feature dims [4l, 4l+4); head = l/4.
// ---------------------------------------------------------------------------
__global__ void aggregate_kernel(const float* __restrict__ bias,
                                 const float* __restrict__ prelu_a,
                                 float* __restrict__ out_pos) {
    const int warp = (blockIdx.x * blockDim.x + threadIdx.x) >> 5;
    if (warp >= N_DST) return;
    const int lane = threadIdx.x & 31;
    const int i = warp;
    const int n = N_SRC + i;
    const int h = lane >> 2;

    const float er_h = g_er[n * NHEAD + h];
    float4 zself = *(const float4*)(g_z + (size_t)n * FDIM + lane * 4);
    float e_self = g_el[n * NHEAD + h] + er_h;
    e_self = (e_self >= 0.f) ? e_self : NEG_SLOPE * e_self;

    float mP = e_self, dP = 1.f;
    float4 aP = zself;
    float mN = e_self, dN = 1.f;
    float4 aN = zself;

    const int pbeg = g_rowptr[i], pend = g_rowptr[i + 1];
    for (int p = pbeg; p < pend; p++) {
        unsigned u = (unsigned)g_packed[p];
        int s = (int)(u & 0x7fffffffu);
        float e = g_el[s * NHEAD + h] + er_h;
        e = (e >= 0.f) ? e : NEG_SLOPE * e;
        float4 zs = *(const float4*)(g_z + (size_t)s * FDIM + lane * 4);
        {   // positive graph: all edges
            float nm = fmaxf(mP, e);
            float sc = __expf(mP - nm);
            float w  = __expf(e - nm);
            mP = nm;
            dP = dP * sc + w;
            aP.x = aP.x * sc + w * zs.x;
            aP.y = aP.y * sc + w * zs.y;
            aP.z = aP.z * sc + w * zs.z;
            aP.w = aP.w * sc + w * zs.w;
        }
        if (u >> 31) {  // negative-graph subset
            float nm = fmaxf(mN, e);
            float sc = __expf(mN - nm);
            float w  = __expf(e - nm);
            mN = nm;
            dN = dN * sc + w;
            aN.x = aN.x * sc + w * zs.x;
            aN.y = aN.y * sc + w * zs.y;
            aN.z = aN.z * sc + w * zs.z;
            aN.w = aN.w * sc + w * zs.w;
        }
    }

    const float pa = prelu_a[0];
    const int f0 = lane * 4;
    float b0 = bias[f0], b1 = bias[f0 + 1], b2 = bias[f0 + 2], b3 = bias[f0 + 3];

    // positive
    {
        float inv = 1.f / dP;
        float v0 = aP.x * inv + b0; v0 = (v0 >= 0.f) ? v0 : pa * v0;
        float v1 = aP.y * inv + b1; v1 = (v1 >= 0.f) ? v1 : pa * v1;
        float v2 = aP.z * inv + b2; v2 = (v2 >= 0.f) ? v2 : pa * v2;
        float v3 = aP.w * inv + b3; v3 = (v3 >= 0.f) ? v3 : pa * v3;
        #pragma unroll
        for (int off = 4; off <= 16; off <<= 1) {
            v0 += __shfl_xor_sync(0xffffffffu, v0, off);
            v1 += __shfl_xor_sync(0xffffffffu, v1, off);
            v2 += __shfl_xor_sync(0xffffffffu, v2, off);
            v3 += __shfl_xor_sync(0xffffffffu, v3, off);
        }
        if (lane < 4) {
            float* o = out_pos + (size_t)i * HDIM + lane * 4;
            o[0] = v0 * 0.125f; o[1] = v1 * 0.125f;
            o[2] = v2 * 0.125f; o[3] = v3 * 0.125f;
        }
    }
    // negative
    {
        float inv = 1.f / dN;
        float v0 = aN.x * inv + b0; v0 = (v0 >= 0.f) ? v0 : pa * v0;
        float v1 = aN.y * inv + b1; v1 = (v1 >= 0.f) ? v1 : pa * v1;
        float v2 = aN.z * inv + b2; v2 = (v2 >= 0.f) ? v2 : pa * v2;
        float v3 = aN.w * inv + b3; v3 = (v3 >= 0.f) ? v3 : pa * v3;
        #pragma unroll
        for (int off = 4; off <= 16; off <<= 1) {
            v0 += __shfl_xor_sync(0xffffffffu, v0, off);
            v1 += __shfl_xor_sync(0xffffffffu, v1, off);
            v2 += __shfl_xor_sync(0xffffffffu, v2, off);
            v3 += __shfl_xor_sync(0xffffffffu, v3, off);
        }
        if (lane < 4) {
            float* o = g_hneg + (size_t)i * HDIM + lane * 4;
            o[0] = v0 * 0.125f; o[1] = v1 * 0.125f;
            o[2] = v2 * 0.125f; o[3] = v3 * 0.125f;
        }
    }
}

// ---------------------------------------------------------------------------
// 4) loss = log(sum(exp(cos(h_pos, h_neg)/TEM)))
// ---------------------------------------------------------------------------
__global__ void loss_kernel(const float* __restrict__ hpos, float* __restrict__ out) {
    __shared__ float red[256];
    float local = 0.f;
    for (int i = threadIdx.x; i < N_DST; i += 256) {
        float dot = 0.f, na = 0.f, nb = 0.f;
        #pragma unroll
        for (int j = 0; j < HDIM; j++) {
            float a = hpos[(size_t)i * HDIM + j];
            float b = g_hneg[(size_t)i * HDIM + j];
            dot += a * b; na += a * a; nb += b * b;
        }
        na = fmaxf(sqrtf(na), 1e-8f);
        nb = fmaxf(sqrtf(nb), 1e-8f);
        local += __expf(dot / (na * nb) / TEM);
    }
    red[threadIdx.x] = local;
    __syncthreads();
    for (int s = 128; s > 0; s >>= 1) {
        if (threadIdx.x < s) red[threadIdx.x] += red[threadIdx.x + s];
        __syncthreads();
    }
    if (threadIdx.x == 0) out[0] = logf(red[0]);
}

// ---------------------------------------------------------------------------
extern "C" void kernel_launch(void* const* d_in, const int* in_sizes, int n_in,
                              void* d_out, int out_size) {
    const float* feat    = (const float*)d_in[0];
    const float* fc_w    = (const float*)d_in[1];
    const float* attn_l  = (const float*)d_in[2];
    const float* attn_r  = (const float*)d_in[3];
    const float* bias    = (const float*)d_in[4];
    const float* prelu_a = (const float*)d_in[5];
    const int*   edge_src = (const int*)d_in[6];
    const int*   edge_dst = (const int*)d_in[7];
    const int*   neg_idx  = (const int*)d_in[8];
    const int    e_neg = in_sizes[8];

    float* out = (float*)d_out;          // [0] = loss, [1..] = h_pos (N_DST x 16)
    float* out_pos = out + 1;

    gemm_el_er_kernel<<<N_NODES / 8, dim3(32, 8)>>>(feat, fc_w, attn_l, attn_r);
    zero_kernel<<<(E_TOT + 255) / 256, 256>>>();
    flags_kernel<<<(e_neg + 255) / 256, 256>>>(neg_idx, e_neg);
    hist_kernel<<<(E_TOT + 255) / 256, 256>>>(edge_dst);
    scan_kernel<<<1, 1024>>>();
    scatter_kernel<<<(E_TOT + 255) / 256, 256>>>(edge_src, edge_dst);
    aggregate_kernel<<<(N_DST + 7) / 8, 256>>>(bias, prelu_a, out_pos);
    loss_kernel<<<1, 256>>>(out_pos, out);
}

// round 5
// speedup vs baseline: 1.6122x; 1.6122x over previous
#include <cuda_runtime.h>
#include <cstdint>

// Problem constants (match reference)
#define N_SRC   20000
#define N_DST   20000
#define N_NODES 40000
#define E_TOT   320000
#define NHEAD   8
#define HDIM    16
#define FDIM    128
#define TEM     0.7f
#define NEG_SLOPE 0.2f
#define E_SHIFT 10.0f   // constant softmax shift; cancels in alpha = w / sum(w)

// Scratch (device globals; no allocations allowed)
__device__ float g_z[N_NODES * FDIM];        // 20.5 MB, L2-resident
__device__ float g_el[N_NODES * NHEAD];
__device__ float g_er[N_NODES * NHEAD];
__device__ int   g_counts[N_DST];
__device__ int   g_rowptr[N_DST + 1];
__device__ int   g_cursor[N_DST];
__device__ int   g_packed[E_TOT];            // src | (neg_flag << 31)
__device__ unsigned char g_flags[E_TOT];
__device__ float g_hneg[N_DST * HDIM];
// B fragments in mma lane order: [kstep 0..15][ntile 0..15][lane 0..31] = (b0hi,b1hi,b0lo,b1lo)
__device__ float4 g_bfrag[16 * 16 * 32];

__device__ __forceinline__ float tf32_hi(float x) {
    return __uint_as_float(__float_as_uint(x) & 0xFFFFE000u);
}

__device__ __forceinline__ void mma_tf32(float* d, unsigned a0, unsigned a1,
                                         unsigned a2, unsigned a3,
                                         unsigned b0, unsigned b1) {
    asm volatile(
        "mma.sync.aligned.m16n8k8.row.col.f32.tf32.tf32.f32 "
        "{%0,%1,%2,%3}, {%4,%5,%6,%7}, {%8,%9}, {%0,%1,%2,%3};\n"
        : "+f"(d[0]), "+f"(d[1]), "+f"(d[2]), "+f"(d[3])
        : "r"(a0), "r"(a1), "r"(a2), "r"(a3), "r"(b0), "r"(b1));
}

// ---------------------------------------------------------------------------
// 0) Pre-swizzle fc_w (128x128) into mma.m16n8k8 B-fragment order with hi/lo
//    tf32 split. 8192 threads, runs once per launch (~1 us).
// ---------------------------------------------------------------------------
__global__ void bprep_kernel(const float* __restrict__ fc_w) {
    int i = blockIdx.x * blockDim.x + threadIdx.x;
    if (i >= 16 * 16 * 32) return;
    int lane = i & 31;
    int nt = (i >> 5) & 15;
    int ks = i >> 9;
    int k = ks * 8 + (lane & 3);       // threadID_in_group -> k row
    int n = nt * 8 + (lane >> 2);      // groupID -> n col
    float b0 = fc_w[k * FDIM + n];
    float b1 = fc_w[(k + 4) * FDIM + n];
    float b0h = tf32_hi(b0), b1h = tf32_hi(b1);
    g_bfrag[i] = make_float4(b0h, b1h, b0 - b0h, b1 - b1h);
}

// ---------------------------------------------------------------------------
// 1) z = feat @ fc_w via tf32 tensor cores, 3xTF32 split (hi*hi+lo*hi+hi*lo).
//    One warp computes a 16x128 tile. No smem, no syncs.
// ---------------------------------------------------------------------------
__global__ void __launch_bounds__(256) gemm_kernel(const float* __restrict__ feat) {
    const int gw = (blockIdx.x * blockDim.x + threadIdx.x) >> 5;
    const int row0 = gw * 16;
    if (row0 >= N_NODES) return;
    const int lane = threadIdx.x & 31;
    const int g = lane >> 2;       // groupID (row within tile)
    const int tg = lane & 3;       // threadID_in_group (k within step)

    const float* ar0 = feat + (size_t)(row0 + g) * FDIM;
    const float* ar1 = ar0 + 8 * FDIM;

    float acc[16][4];
    #pragma unroll
    for (int nt = 0; nt < 16; nt++) {
        acc[nt][0] = 0.f; acc[nt][1] = 0.f; acc[nt][2] = 0.f; acc[nt][3] = 0.f;
    }

    #pragma unroll 1
    for (int ks = 0; ks < 16; ks++) {
        float a0 = ar0[ks * 8 + tg];
        float a1 = ar1[ks * 8 + tg];
        float a2 = ar0[ks * 8 + tg + 4];
        float a3 = ar1[ks * 8 + tg + 4];
        unsigned h0 = __float_as_uint(a0) & 0xFFFFE000u;
        unsigned h1 = __float_as_uint(a1) & 0xFFFFE000u;
        unsigned h2 = __float_as_uint(a2) & 0xFFFFE000u;
        unsigned h3 = __float_as_uint(a3) & 0xFFFFE000u;
        unsigned l0 = __float_as_uint(a0 - __uint_as_float(h0));
        unsigned l1 = __float_as_uint(a1 - __uint_as_float(h1));
        unsigned l2 = __float_as_uint(a2 - __uint_as_float(h2));
        unsigned l3 = __float_as_uint(a3 - __uint_as_float(h3));

        const float4* bp = g_bfrag + ks * 16 * 32 + lane;
        #pragma unroll
        for (int nt = 0; nt < 16; nt++) {
            float4 b = bp[nt * 32];
            unsigned bx = __float_as_uint(b.x), by = __float_as_uint(b.y);
            unsigned bz = __float_as_uint(b.z), bw = __float_as_uint(b.w);
            mma_tf32(acc[nt], h0, h1, h2, h3, bx, by);   // hi * hi
            mma_tf32(acc[nt], l0, l1, l2, l3, bx, by);   // lo * hi
            mma_tf32(acc[nt], h0, h1, h2, h3, bz, bw);   // hi * lo
        }
    }

    float* zr0 = g_z + (size_t)(row0 + g) * FDIM;
    float* zr1 = zr0 + 8 * FDIM;
    #pragma unroll
    for (int nt = 0; nt < 16; nt++) {
        *(float2*)(zr0 + nt * 8 + tg * 2) = make_float2(acc[nt][0], acc[nt][1]);
        *(float2*)(zr1 + nt * 8 + tg * 2) = make_float2(acc[nt][2], acc[nt][3]);
    }
}

// ---------------------------------------------------------------------------
// 1b) el/er from z (L2-resident). One warp per row.
// ---------------------------------------------------------------------------
__global__ void elr_kernel(const float* __restrict__ attn_l,
                           const float* __restrict__ attn_r) {
    const int row = (blockIdx.x * blockDim.x + threadIdx.x) >> 5;
    if (row >= N_NODES) return;
    const int lane = threadIdx.x & 31;
    const int h = lane >> 2, d0 = (lane & 3) * 4;
    float4 zz = *(const float4*)(g_z + (size_t)row * FDIM + lane * 4);
    const float* al = attn_l + h * HDIM + d0;
    const float* ar = attn_r + h * HDIM + d0;
    float elp = zz.x * al[0] + zz.y * al[1] + zz.z * al[2] + zz.w * al[3];
    float erp = zz.x * ar[0] + zz.y * ar[1] + zz.z * ar[2] + zz.w * ar[3];
    elp += __shfl_xor_sync(0xffffffffu, elp, 1);
    elp += __shfl_xor_sync(0xffffffffu, elp, 2);
    erp += __shfl_xor_sync(0xffffffffu, erp, 1);
    erp += __shfl_xor_sync(0xffffffffu, erp, 2);
    if ((lane & 3) == 0) {
        g_el[row * NHEAD + h] = elp;
        g_er[row * NHEAD + h] = erp;
    }
}

// ---------------------------------------------------------------------------
// 2) CSR build over dst nodes
// ---------------------------------------------------------------------------
__global__ void zero_kernel() {
    int i = blockIdx.x * blockDim.x + threadIdx.x;
    if (i < E_TOT / 4) ((int*)g_flags)[i] = 0;
    if (i < N_DST) g_counts[i] = 0;
}

__global__ void flags_kernel(const int* __restrict__ neg_idx, int e_neg) {
    int i = blockIdx.x * blockDim.x + threadIdx.x;
    if (i < e_neg) g_flags[neg_idx[i]] = 1;
}

__global__ void hist_kernel(const int* __restrict__ edge_dst) {
    int i = blockIdx.x * blockDim.x + threadIdx.x;
    if (i >= E_TOT / 4) return;
    int4 d = ((const int4*)edge_dst)[i];
    atomicAdd(&g_counts[d.x - N_SRC], 1);
    atomicAdd(&g_counts[d.y - N_SRC], 1);
    atomicAdd(&g_counts[d.z - N_SRC], 1);
    atomicAdd(&g_counts[d.w - N_SRC], 1);
}

// Single block, 1024 threads, 20 elements/thread; 2 barriers total.
__global__ void scan_kernel() {
    const int PER = 20;  // 1024*20 = 20480 >= N_DST
    __shared__ int ws[32];
    const int t = threadIdx.x;
    const int lane = t & 31, wid = t >> 5;
    const int base = t * PER;

    int loc[PER];
    int s = 0;
    #pragma unroll
    for (int j = 0; j < PER; j++) {
        int idx = base + j;
        int v = (idx < N_DST) ? g_counts[idx] : 0;
        loc[j] = s;
        s += v;
    }
    // inclusive warp scan of s
    int inc = s;
    #pragma unroll
    for (int off = 1; off < 32; off <<= 1) {
        int v = __shfl_up_sync(0xffffffffu, inc, off);
        if (lane >= off) inc += v;
    }
    if (lane == 31) ws[wid] = inc;
    __syncthreads();
    if (wid == 0) {
        int v = ws[lane];
        int winc = v;
        #pragma unroll
        for (int off = 1; off < 32; off <<= 1) {
            int u = __shfl_up_sync(0xffffffffu, winc, off);
            if (lane >= off) winc += u;
        }
        ws[lane] = winc - v;  // exclusive warp offset
    }
    __syncthreads();
    int off = ws[wid] + inc - s;  // exclusive thread offset
    #pragma unroll
    for (int j = 0; j < PER; j++) {
        int idx = base + j;
        if (idx < N_DST) {
            int e = off + loc[j];
            g_rowptr[idx] = e;
            g_cursor[idx] = e;
        }
    }
    if (t == 1023) g_rowptr[N_DST] = off + s;
}

__global__ void scatter_kernel(const int* __restrict__ edge_src,
                               const int* __restrict__ edge_dst) {
    int i = blockIdx.x * blockDim.x + threadIdx.x;
    if (i >= E_TOT / 4) return;
    int4 sv = ((const int4*)edge_src)[i];
    int4 dv = ((const int4*)edge_dst)[i];
    int b = i * 4;
    int p0 = atomicAdd(&g_cursor[dv.x - N_SRC], 1);
    g_packed[p0] = sv.x | ((int)g_flags[b + 0] << 31);
    int p1 = atomicAdd(&g_cursor[dv.y - N_SRC], 1);
    g_packed[p1] = sv.y | ((int)g_flags[b + 1] << 31);
    int p2 = atomicAdd(&g_cursor[dv.z - N_SRC], 1);
    g_packed[p2] = sv.z | ((int)g_flags[b + 2] << 31);
    int p3 = atomicAdd(&g_cursor[dv.w - N_SRC], 1);
    g_packed[p3] = sv.w | ((int)g_flags[b + 3] << 31);
}

// ---------------------------------------------------------------------------
// 3) Aggregation: one warp per dst node, fused pos+neg, shift-based softmax
//    (no running max — constant shift cancels in alpha), 1-edge prefetch.
// ---------------------------------------------------------------------------
__global__ void aggregate_kernel(const float* __restrict__ bias,
                                 const float* __restrict__ prelu_a,
                                 float* __restrict__ out_pos) {
    const int warp = (blockIdx.x * blockDim.x + threadIdx.x) >> 5;
    if (warp >= N_DST) return;
    const int lane = threadIdx.x & 31;
    const int i = warp;
    const int n = N_SRC + i;
    const int h = lane >> 2;

    const float er_h = g_er[n * NHEAD + h];
    float4 zself = *(const float4*)(g_z + (size_t)n * FDIM + lane * 4);
    float e_self = g_el[n * NHEAD + h] + er_h;
    e_self = (e_self >= 0.f) ? e_self : NEG_SLOPE * e_self;
    float ws = __expf(e_self - E_SHIFT);

    float dP = ws, dN = ws;
    float4 aP = make_float4(ws * zself.x, ws * zself.y, ws * zself.z, ws * zself.w);
    float4 aN = aP;

    const int pbeg = g_rowptr[i], pend = g_rowptr[i + 1];
    int p = pbeg;
    unsigned u_n = 0u; float el_n = 0.f;
    float4 z_n = make_float4(0.f, 0.f, 0.f, 0.f);
    if (p < pend) {
        u_n = (unsigned)g_packed[p];
        int s = (int)(u_n & 0x7fffffffu);
        el_n = g_el[s * NHEAD + h];
        z_n = *(const float4*)(g_z + (size_t)s * FDIM + lane * 4);
    }
    while (p < pend) {
        unsigned u = u_n; float elv = el_n; float4 zs = z_n;
        int pn = p + 1;
        if (pn < pend) {  // prefetch next edge while processing current
            u_n = (unsigned)g_packed[pn];
            int s2 = (int)(u_n & 0x7fffffffu);
            el_n = g_el[s2 * NHEAD + h];
            z_n = *(const float4*)(g_z + (size_t)s2 * FDIM + lane * 4);
        }
        float e = elv + er_h;
        e = (e >= 0.f) ? e : NEG_SLOPE * e;
        float w = __expf(e - E_SHIFT);
        dP += w;
        aP.x += w * zs.x; aP.y += w * zs.y; aP.z += w * zs.z; aP.w += w * zs.w;
        if (u >> 31) {
            dN += w;
            aN.x += w * zs.x; aN.y += w * zs.y; aN.z += w * zs.z; aN.w += w * zs.w;
        }
        p = pn;
    }

    const float pa = prelu_a[0];
    const int f0 = lane * 4;
    float b0 = bias[f0], b1 = bias[f0 + 1], b2 = bias[f0 + 2], b3 = bias[f0 + 3];

    {   // positive
        float inv = 1.f / dP;
        float v0 = aP.x * inv + b0; v0 = (v0 >= 0.f) ? v0 : pa * v0;
        float v1 = aP.y * inv + b1; v1 = (v1 >= 0.f) ? v1 : pa * v1;
        float v2 = aP.z * inv + b2; v2 = (v2 >= 0.f) ? v2 : pa * v2;
        float v3 = aP.w * inv + b3; v3 = (v3 >= 0.f) ? v3 : pa * v3;
        #pragma unroll
        for (int off = 4; off <= 16; off <<= 1) {
            v0 += __shfl_xor_sync(0xffffffffu, v0, off);
            v1 += __shfl_xor_sync(0xffffffffu, v1, off);
            v2 += __shfl_xor_sync(0xffffffffu, v2, off);
            v3 += __shfl_xor_sync(0xffffffffu, v3, off);
        }
        if (lane < 4) {
            float* o = out_pos + (size_t)i * HDIM + lane * 4;
            o[0] = v0 * 0.125f; o[1] = v1 * 0.125f;
            o[2] = v2 * 0.125f; o[3] = v3 * 0.125f;
        }
    }
    {   // negative
        float inv = 1.f / dN;
        float v0 = aN.x * inv + b0; v0 = (v0 >= 0.f) ? v0 : pa * v0;
        float v1 = aN.y * inv + b1; v1 = (v1 >= 0.f) ? v1 : pa * v1;
        float v2 = aN.z * inv + b2; v2 = (v2 >= 0.f) ? v2 : pa * v2;
        float v3 = aN.w * inv + b3; v3 = (v3 >= 0.f) ? v3 : pa * v3;
        #pragma unroll
        for (int off = 4; off <= 16; off <<= 1) {
            v0 += __shfl_xor_sync(0xffffffffu, v0, off);
            v1 += __shfl_xor_sync(0xffffffffu, v1, off);
            v2 += __shfl_xor_sync(0xffffffffu, v2, off);
            v3 += __shfl_xor_sync(0xffffffffu, v3, off);
        }
        if (lane < 4) {
            float* o = g_hneg + (size_t)i * HDIM + lane * 4;
            o[0] = v0 * 0.125f; o[1] = v1 * 0.125f;
            o[2] = v2 * 0.125f; o[3] = v3 * 0.125f;
        }
    }
}

// ---------------------------------------------------------------------------
// 4) loss = log(sum(exp(cos(h_pos, h_neg)/TEM)))   (hpos is 4B-misaligned for
//    float4 — scalar loads there, float4 for g_hneg)
// ---------------------------------------------------------------------------
__global__ void loss_kernel(const float* __restrict__ hpos, float* __restrict__ out) {
    __shared__ float red[1024];
    float local = 0.f;
    for (int i = threadIdx.x; i < N_DST; i += 1024) {
        const float* a = hpos + (size_t)i * HDIM;
        const float4* b4 = (const float4*)(g_hneg + (size_t)i * HDIM);
        float dot = 0.f, na = 0.f, nb = 0.f;
        #pragma unroll
        for (int j = 0; j < 4; j++) {
            float4 b = b4[j];
            float a0 = a[j * 4], a1 = a[j * 4 + 1], a2 = a[j * 4 + 2], a3 = a[j * 4 + 3];
            dot += a0 * b.x + a1 * b.y + a2 * b.z + a3 * b.w;
            na  += a0 * a0 + a1 * a1 + a2 * a2 + a3 * a3;
            nb  += b.x * b.x + b.y * b.y + b.z * b.z + b.w * b.w;
        }
        na = fmaxf(sqrtf(na), 1e-8f);
        nb = fmaxf(sqrtf(nb), 1e-8f);
        local += __expf(dot / (na * nb) / TEM);
    }
    red[threadIdx.x] = local;
    __syncthreads();
    for (int s = 512; s > 0; s >>= 1) {
        if (threadIdx.x < s) red[threadIdx.x] += red[threadIdx.x + s];
        __syncthreads();
    }
    if (threadIdx.x == 0) out[0] = logf(red[0]);
}

// ---------------------------------------------------------------------------
extern "C" void kernel_launch(void* const* d_in, const int* in_sizes, int n_in,
                              void* d_out, int out_size) {
    const float* feat    = (const float*)d_in[0];
    const float* fc_w    = (const float*)d_in[1];
    const float* attn_l  = (const float*)d_in[2];
    const float* attn_r  = (const float*)d_in[3];
    const float* bias    = (const float*)d_in[4];
    const float* prelu_a = (const float*)d_in[5];
    const int*   edge_src = (const int*)d_in[6];
    const int*   edge_dst = (const int*)d_in[7];
    const int*   neg_idx  = (const int*)d_in[8];
    const int    e_neg = in_sizes[8];

    float* out = (float*)d_out;          // [0] = loss, [1..] = h_pos (N_DST x 16)
    float* out_pos = out + 1;

    bprep_kernel<<<32, 256>>>(fc_w);
    gemm_kernel<<<(N_NODES / 16 * 32 + 255) / 256, 256>>>(feat);
    elr_kernel<<<N_NODES / 8, 256>>>(attn_l, attn_r);
    zero_kernel<<<(E_TOT / 4 + 255) / 256, 256>>>();
    flags_kernel<<<(e_neg + 255) / 256, 256>>>(neg_idx, e_neg);
    hist_kernel<<<(E_TOT / 4 + 255) / 256, 256>>>(edge_dst);
    scan_kernel<<<1, 1024>>>();
    scatter_kernel<<<(E_TOT / 4 + 255) / 256, 256>>>(edge_src, edge_dst);
    aggregate_kernel<<<(N_DST + 7) / 8, 256>>>(bias, prelu_a, out_pos);
    loss_kernel<<<1, 1024>>>(out_pos, out);
}

// round 6
// speedup vs baseline: 1.8679x; 1.1586x over previous
#include <cuda_runtime.h>
#include <cstdint>

// Problem constants (match reference)
#define N_SRC   20000
#define N_DST   20000
#define N_NODES 40000
#define E_TOT   320000
#define NHEAD   8
#define HDIM    16
#define FDIM    128
#define TEM     0.7f
#define NEG_SLOPE 0.2f
#define E_SHIFT 10.0f   // constant softmax shift; cancels in alpha = w / sum(w)

// Scratch (device globals; zero-initialized at module load; every launch
// restores them to zero where required -> deterministic across graph replays)
__device__ float g_z[N_NODES * FDIM];        // 20.5 MB, L2-resident
__device__ float g_el[N_NODES * NHEAD];
__device__ float g_er[N_NODES * NHEAD];
__device__ int   g_counts[N_DST];            // zeroed by scan after reading
__device__ int   g_rowptr[N_DST + 1];
__device__ int   g_cursor[N_DST];
__device__ int   g_packed[E_TOT];            // src | (neg_flag << 31)
__device__ unsigned char g_flags[E_TOT];     // zeroed by scatter after reading
__device__ float g_hneg[N_DST * HDIM];
__device__ float g_loss;                     // zeroed by finalize after reading
// B fragments in mma lane order: [kstep 0..15][ntile 0..15][lane 0..31] = (b0hi,b1hi,b0lo,b1lo)
__device__ float4 g_bfrag[16 * 16 * 32];

__device__ __forceinline__ float tf32_hi(float x) {
    return __uint_as_float(__float_as_uint(x) & 0xFFFFE000u);
}

__device__ __forceinline__ void mma_tf32(float* d, unsigned a0, unsigned a1,
                                         unsigned a2, unsigned a3,
                                         unsigned b0, unsigned b1) {
    asm volatile(
        "mma.sync.aligned.m16n8k8.row.col.f32.tf32.tf32.f32 "
        "{%0,%1,%2,%3}, {%4,%5,%6,%7}, {%8,%9}, {%0,%1,%2,%3};\n"
        : "+f"(d[0]), "+f"(d[1]), "+f"(d[2]), "+f"(d[3])
        : "r"(a0), "r"(a1), "r"(a2), "r"(a3), "r"(b0), "r"(b1));
}

// ---------------------------------------------------------------------------
// 0) Pre-swizzle fc_w (128x128) into mma.m16n8k8 B-fragment order with hi/lo
//    tf32 split.
// ---------------------------------------------------------------------------
__global__ void bprep_kernel(const float* __restrict__ fc_w) {
    int i = blockIdx.x * blockDim.x + threadIdx.x;
    if (i >= 16 * 16 * 32) return;
    int lane = i & 31;
    int nt = (i >> 5) & 15;
    int ks = i >> 9;
    int k = ks * 8 + (lane & 3);       // threadID_in_group -> k row
    int n = nt * 8 + (lane >> 2);      // groupID -> n col
    float b0 = fc_w[k * FDIM + n];
    float b1 = fc_w[(k + 4) * FDIM + n];
    float b0h = tf32_hi(b0), b1h = tf32_hi(b1);
    g_bfrag[i] = make_float4(b0h, b1h, b0 - b0h, b1 - b1h);
}

// ---------------------------------------------------------------------------
// 1) flags + hist fused (independent target arrays, no ordering needed)
// ---------------------------------------------------------------------------
__global__ void flagshist_kernel(const int* __restrict__ neg_idx, int e_neg,
                                 const int* __restrict__ edge_dst) {
    int i = blockIdx.x * blockDim.x + threadIdx.x;
    if (i < E_TOT / 4) {
        int4 d = ((const int4*)edge_dst)[i];
        atomicAdd(&g_counts[d.x - N_SRC], 1);
        atomicAdd(&g_counts[d.y - N_SRC], 1);
        atomicAdd(&g_counts[d.z - N_SRC], 1);
        atomicAdd(&g_counts[d.w - N_SRC], 1);
    }
    if (i < e_neg) g_flags[neg_idx[i]] = 1;
}

// ---------------------------------------------------------------------------
// 2) Exclusive scan: single block, 1024 threads, 20 elems/thread, 2 barriers.
//    Restores g_counts to zero for the next replay.
// ---------------------------------------------------------------------------
__global__ void scan_kernel() {
    const int PER = 20;  // 1024*20 = 20480 >= N_DST
    __shared__ int ws[32];
    const int t = threadIdx.x;
    const int lane = t & 31, wid = t >> 5;
    const int base = t * PER;

    int loc[PER];
    int s = 0;
    #pragma unroll
    for (int j = 0; j < PER; j++) {
        int idx = base + j;
        int v = (idx < N_DST) ? g_counts[idx] : 0;
        loc[j] = s;
        s += v;
    }
    int inc = s;
    #pragma unroll
    for (int off = 1; off < 32; off <<= 1) {
        int v = __shfl_up_sync(0xffffffffu, inc, off);
        if (lane >= off) inc += v;
    }
    if (lane == 31) ws[wid] = inc;
    __syncthreads();
    if (wid == 0) {
        int v = ws[lane];
        int winc = v;
        #pragma unroll
        for (int off = 1; off < 32; off <<= 1) {
            int u = __shfl_up_sync(0xffffffffu, winc, off);
            if (lane >= off) winc += u;
        }
        ws[lane] = winc - v;  // exclusive warp offset
    }
    __syncthreads();
    int off = ws[wid] + inc - s;  // exclusive thread offset
    #pragma unroll
    for (int j = 0; j < PER; j++) {
        int idx = base + j;
        if (idx < N_DST) {
            int e = off + loc[j];
            g_rowptr[idx] = e;
            g_cursor[idx] = e;
            g_counts[idx] = 0;   // restore invariant for next replay
        }
    }
    if (t == 1023) g_rowptr[N_DST] = off + s;
}

// ---------------------------------------------------------------------------
// 3) z = feat @ fc_w via tf32 tensor cores, 3xTF32 split; el/er fused into
//    the epilogue (accumulators already in registers). One warp = 16x128 tile.
// ---------------------------------------------------------------------------
__global__ void __launch_bounds__(256) gemm_kernel(const float* __restrict__ feat,
                                                   const float* __restrict__ attn_l,
                                                   const float* __restrict__ attn_r) {
    const int gw = (blockIdx.x * blockDim.x + threadIdx.x) >> 5;
    const int row0 = gw * 16;
    if (row0 >= N_NODES) return;
    const int lane = threadIdx.x & 31;
    const int g = lane >> 2;       // groupID (row within tile)
    const int tg = lane & 3;       // threadID_in_group

    const float* ar0 = feat + (size_t)(row0 + g) * FDIM;
    const float* ar1 = ar0 + 8 * FDIM;

    float acc[16][4];
    #pragma unroll
    for (int nt = 0; nt < 16; nt++) {
        acc[nt][0] = 0.f; acc[nt][1] = 0.f; acc[nt][2] = 0.f; acc[nt][3] = 0.f;
    }

    #pragma unroll 1
    for (int ks = 0; ks < 16; ks++) {
        float a0 = ar0[ks * 8 + tg];
        float a1 = ar1[ks * 8 + tg];
        float a2 = ar0[ks * 8 + tg + 4];
        float a3 = ar1[ks * 8 + tg + 4];
        unsigned h0 = __float_as_uint(a0) & 0xFFFFE000u;
        unsigned h1 = __float_as_uint(a1) & 0xFFFFE000u;
        unsigned h2 = __float_as_uint(a2) & 0xFFFFE000u;
        unsigned h3 = __float_as_uint(a3) & 0xFFFFE000u;
        unsigned l0 = __float_as_uint(a0 - __uint_as_float(h0));
        unsigned l1 = __float_as_uint(a1 - __uint_as_float(h1));
        unsigned l2 = __float_as_uint(a2 - __uint_as_float(h2));
        unsigned l3 = __float_as_uint(a3 - __uint_as_float(h3));

        const float4* bp = g_bfrag + ks * 16 * 32 + lane;
        #pragma unroll
        for (int nt = 0; nt < 16; nt++) {
            float4 b = bp[nt * 32];
            unsigned bx = __float_as_uint(b.x), by = __float_as_uint(b.y);
            unsigned bz = __float_as_uint(b.z), bw = __float_as_uint(b.w);
            mma_tf32(acc[nt], h0, h1, h2, h3, bx, by);   // hi * hi
            mma_tf32(acc[nt], l0, l1, l2, l3, bx, by);   // lo * hi
            mma_tf32(acc[nt], h0, h1, h2, h3, bz, bw);   // hi * lo
        }
    }

    // store z
    float* zr0 = g_z + (size_t)(row0 + g) * FDIM;
    float* zr1 = zr0 + 8 * FDIM;
    #pragma unroll
    for (int nt = 0; nt < 16; nt++) {
        *(float2*)(zr0 + nt * 8 + tg * 2) = make_float2(acc[nt][0], acc[nt][1]);
        *(float2*)(zr1 + nt * 8 + tg * 2) = make_float2(acc[nt][2], acc[nt][3]);
    }

    // fused el/er epilogue: head h uses cols [16h, 16h+16) = ntiles {2h, 2h+1};
    // each thread holds cols c0=nt*8+tg*2, c0+1 for rows g and g+8.
    const int rA = (row0 + g) * NHEAD;
    const int rB = (row0 + g + 8) * NHEAD;
    #pragma unroll
    for (int h = 0; h < NHEAD; h++) {
        const int nt0 = 2 * h, nt1 = 2 * h + 1;
        const int c0 = nt0 * 8 + tg * 2;
        const int c1 = nt1 * 8 + tg * 2;
        float2 al0 = *(const float2*)(attn_l + c0);
        float2 al1 = *(const float2*)(attn_l + c1);
        float2 arr0 = *(const float2*)(attn_r + c0);
        float2 arr1 = *(const float2*)(attn_r + c1);
        float elA = acc[nt0][0] * al0.x + acc[nt0][1] * al0.y
                  + acc[nt1][0] * al1.x + acc[nt1][1] * al1.y;
        float elB = acc[nt0][2] * al0.x + acc[nt0][3] * al0.y
                  + acc[nt1][2] * al1.x + acc[nt1][3] * al1.y;
        float erA = acc[nt0][0] * arr0.x + acc[nt0][1] * arr0.y
                  + acc[nt1][0] * arr1.x + acc[nt1][1] * arr1.y;
        float erB = acc[nt0][2] * arr0.x + acc[nt0][3] * arr0.y
                  + acc[nt1][2] * arr1.x + acc[nt1][3] * arr1.y;
        elA += __shfl_xor_sync(0xffffffffu, elA, 1);
        elA += __shfl_xor_sync(0xffffffffu, elA, 2);
        elB += __shfl_xor_sync(0xffffffffu, elB, 1);
        elB += __shfl_xor_sync(0xffffffffu, elB, 2);
        erA += __shfl_xor_sync(0xffffffffu, erA, 1);
        erA += __shfl_xor_sync(0xffffffffu, erA, 2);
        erB += __shfl_xor_sync(0xffffffffu, erB, 1);
        erB += __shfl_xor_sync(0xffffffffu, erB, 2);
        if (tg == 0) {
            g_el[rA + h] = elA;
            g_el[rB + h] = elB;
            g_er[rA + h] = erA;
            g_er[rB + h] = erB;
        }
    }
}

// ---------------------------------------------------------------------------
// 4) Scatter edges into CSR; restores g_flags to zero after reading.
// ---------------------------------------------------------------------------
__global__ void scatter_kernel(const int* __restrict__ edge_src,
                               const int* __restrict__ edge_dst) {
    int i = blockIdx.x * blockDim.x + threadIdx.x;
    if (i >= E_TOT / 4) return;
    int4 sv = ((const int4*)edge_src)[i];
    int4 dv = ((const int4*)edge_dst)[i];
    int fl = ((const int*)g_flags)[i];
    ((int*)g_flags)[i] = 0;              // restore invariant for next replay
    int p0 = atomicAdd(&g_cursor[dv.x - N_SRC], 1);
    g_packed[p0] = sv.x | ((fl & 1) << 31);
    int p1 = atomicAdd(&g_cursor[dv.y - N_SRC], 1);
    g_packed[p1] = sv.y | (((fl >> 8) & 1) << 31);
    int p2 = atomicAdd(&g_cursor[dv.z - N_SRC], 1);
    g_packed[p2] = sv.z | (((fl >> 16) & 1) << 31);
    int p3 = atomicAdd(&g_cursor[dv.w - N_SRC], 1);
    g_packed[p3] = sv.w | (((fl >> 24) & 1) << 31);
}

// ---------------------------------------------------------------------------
// 5) Aggregation: one warp per dst node, fused pos+neg, shift-softmax,
//    1-edge prefetch, per-node loss contribution fused (atomicAdd to g_loss).
// ---------------------------------------------------------------------------
__global__ void aggregate_kernel(const float* __restrict__ bias,
                                 const float* __restrict__ prelu_a,
                                 float* __restrict__ out_pos) {
    const int warp = (blockIdx.x * blockDim.x + threadIdx.x) >> 5;
    if (warp >= N_DST) return;
    const int lane = threadIdx.x & 31;
    const int i = warp;
    const int n = N_SRC + i;
    const int h = lane >> 2;

    const float er_h = g_er[n * NHEAD + h];
    float4 zself = *(const float4*)(g_z + (size_t)n * FDIM + lane * 4);
    float e_self = g_el[n * NHEAD + h] + er_h;
    e_self = (e_self >= 0.f) ? e_self : NEG_SLOPE * e_self;
    float ws = __expf(e_self - E_SHIFT);

    float dP = ws, dN = ws;
    float4 aP = make_float4(ws * zself.x, ws * zself.y, ws * zself.z, ws * zself.w);
    float4 aN = aP;

    const int pbeg = g_rowptr[i], pend = g_rowptr[i + 1];
    int p = pbeg;
    unsigned u_n = 0u; float el_n = 0.f;
    float4 z_n = make_float4(0.f, 0.f, 0.f, 0.f);
    if (p < pend) {
        u_n = (unsigned)g_packed[p];
        int s = (int)(u_n & 0x7fffffffu);
        el_n = g_el[s * NHEAD + h];
        z_n = *(const float4*)(g_z + (size_t)s * FDIM + lane * 4);
    }
    while (p < pend) {
        unsigned u = u_n; float elv = el_n; float4 zs = z_n;
        int pn = p + 1;
        if (pn < pend) {  // prefetch next edge while processing current
            u_n = (unsigned)g_packed[pn];
            int s2 = (int)(u_n & 0x7fffffffu);
            el_n = g_el[s2 * NHEAD + h];
            z_n = *(const float4*)(g_z + (size_t)s2 * FDIM + lane * 4);
        }
        float e = elv + er_h;
        e = (e >= 0.f) ? e : NEG_SLOPE * e;
        float w = __expf(e - E_SHIFT);
        dP += w;
        aP.x += w * zs.x; aP.y += w * zs.y; aP.z += w * zs.z; aP.w += w * zs.w;
        if (u >> 31) {
            dN += w;
            aN.x += w * zs.x; aN.y += w * zs.y; aN.z += w * zs.z; aN.w += w * zs.w;
        }
        p = pn;
    }

    const float pa = prelu_a[0];
    const int f0 = lane * 4;
    float b0 = bias[f0], b1 = bias[f0 + 1], b2 = bias[f0 + 2], b3 = bias[f0 + 3];

    float pv0, pv1, pv2, pv3, nv0, nv1, nv2, nv3;
    {   // positive
        float inv = 1.f / dP;
        float v0 = aP.x * inv + b0; v0 = (v0 >= 0.f) ? v0 : pa * v0;
        float v1 = aP.y * inv + b1; v1 = (v1 >= 0.f) ? v1 : pa * v1;
        float v2 = aP.z * inv + b2; v2 = (v2 >= 0.f) ? v2 : pa * v2;
        float v3 = aP.w * inv + b3; v3 = (v3 >= 0.f) ? v3 : pa * v3;
        #pragma unroll
        for (int off = 4; off <= 16; off <<= 1) {
            v0 += __shfl_xor_sync(0xffffffffu, v0, off);
            v1 += __shfl_xor_sync(0xffffffffu, v1, off);
            v2 += __shfl_xor_sync(0xffffffffu, v2, off);
            v3 += __shfl_xor_sync(0xffffffffu, v3, off);
        }
        pv0 = v0 * 0.125f; pv1 = v1 * 0.125f; pv2 = v2 * 0.125f; pv3 = v3 * 0.125f;
        if (lane < 4) {
            float* o = out_pos + (size_t)i * HDIM + lane * 4;
            o[0] = pv0; o[1] = pv1; o[2] = pv2; o[3] = pv3;
        }
    }
    {   // negative
        float inv = 1.f / dN;
        float v0 = aN.x * inv + b0; v0 = (v0 >= 0.f) ? v0 : pa * v0;
        float v1 = aN.y * inv + b1; v1 = (v1 >= 0.f) ? v1 : pa * v1;
        float v2 = aN.z * inv + b2; v2 = (v2 >= 0.f) ? v2 : pa * v2;
        float v3 = aN.w * inv + b3; v3 = (v3 >= 0.f) ? v3 : pa * v3;
        #pragma unroll
        for (int off = 4; off <= 16; off <<= 1) {
            v0 += __shfl_xor_sync(0xffffffffu, v0, off);
            v1 += __shfl_xor_sync(0xffffffffu, v1, off);
            v2 += __shfl_xor_sync(0xffffffffu, v2, off);
            v3 += __shfl_xor_sync(0xffffffffu, v3, off);
        }
        nv0 = v0 * 0.125f; nv1 = v1 * 0.125f; nv2 = v2 * 0.125f; nv3 = v3 * 0.125f;
    }

    // fused loss contribution: every lane holds the j=(lane&3) dim group
    // (duplicated across heads after the reduction); reduce over the 4 groups.
    float dot = pv0 * nv0 + pv1 * nv1 + pv2 * nv2 + pv3 * nv3;
    float na  = pv0 * pv0 + pv1 * pv1 + pv2 * pv2 + pv3 * pv3;
    float nb  = nv0 * nv0 + nv1 * nv1 + nv2 * nv2 + nv3 * nv3;
    dot += __shfl_xor_sync(0xffffffffu, dot, 1);
    dot += __shfl_xor_sync(0xffffffffu, dot, 2);
    na  += __shfl_xor_sync(0xffffffffu, na, 1);
    na  += __shfl_xor_sync(0xffffffffu, na, 2);
    nb  += __shfl_xor_sync(0xffffffffu, nb, 1);
    nb  += __shfl_xor_sync(0xffffffffu, nb, 2);
    if (lane == 0) {
        float den = fmaxf(sqrtf(na), 1e-8f) * fmaxf(sqrtf(nb), 1e-8f);
        atomicAdd(&g_loss, __expf(dot / den / TEM));
    }
}

// ---------------------------------------------------------------------------
// 6) finalize: out[0] = log(sum); reset accumulator for the next replay.
// ---------------------------------------------------------------------------
__global__ void finalize_kernel(float* __restrict__ out) {
    out[0] = logf(g_loss);
    g_loss = 0.f;
}

// ---------------------------------------------------------------------------
extern "C" void kernel_launch(void* const* d_in, const int* in_sizes, int n_in,
                              void* d_out, int out_size) {
    const float* feat    = (const float*)d_in[0];
    const float* fc_w    = (const float*)d_in[1];
    const float* attn_l  = (const float*)d_in[2];
    const float* attn_r  = (const float*)d_in[3];
    const float* bias    = (const float*)d_in[4];
    const float* prelu_a = (const float*)d_in[5];
    const int*   edge_src = (const int*)d_in[6];
    const int*   edge_dst = (const int*)d_in[7];
    const int*   neg_idx  = (const int*)d_in[8];
    const int    e_neg = in_sizes[8];

    float* out = (float*)d_out;          // [0] = loss, [1..] = h_pos (N_DST x 16)
    float* out_pos = out + 1;

    int fh_n = (e_neg > E_TOT / 4) ? e_neg : (E_TOT / 4);

    bprep_kernel<<<32, 256>>>(fc_w);                                          // 0
    flagshist_kernel<<<(fh_n + 255) / 256, 256>>>(neg_idx, e_neg, edge_dst);  // 1
    scan_kernel<<<1, 1024>>>();                                               // 2
    gemm_kernel<<<(N_NODES / 16 * 32 + 255) / 256, 256>>>(feat, attn_l, attn_r); // 3 (profiled)
    scatter_kernel<<<(E_TOT / 4 + 255) / 256, 256>>>(edge_src, edge_dst);     // 4
    aggregate_kernel<<<(N_DST + 7) / 8, 256>>>(bias, prelu_a, out_pos);       // 5
    finalize_kernel<<<1, 1>>>(out);                                           // 6
}

// round 7
// speedup vs baseline: 2.8462x; 1.5238x over previous
#include <cuda_runtime.h>
#include <cstdint>

// Problem constants (match reference)
#define N_SRC   20000
#define N_DST   20000
#define N_NODES 40000
#define E_TOT   320000
#define NHEAD   8
#define HDIM    16
#define FDIM    128
#define TEM     0.7f
#define NEG_SLOPE 0.2f
#define E_SHIFT 10.0f   // constant softmax shift; cancels in alpha = w / sum(w)

// Scratch (device globals; zero-initialized at module load; every launch
// restores them to zero where required -> deterministic across graph replays)
__device__ float g_z[N_NODES * FDIM];        // 20.5 MB, L2-resident
__device__ float g_el[N_NODES * NHEAD];
__device__ float g_er[N_NODES * NHEAD];
__device__ int   g_counts[N_DST];            // zeroed by scan after reading
__device__ int   g_rowptr[N_DST + 1];
__device__ int   g_cursor[N_DST];
__device__ int   g_packed[E_TOT];            // src | (neg_flag << 31)
__device__ unsigned char g_flags[E_TOT];     // zeroed by scatter after reading
__device__ float g_hneg[N_DST * HDIM];
__device__ float g_loss;                     // zeroed by finalize after reading
// B fragments in mma lane order: [kstep 0..15][ntile 0..15][lane 0..31] = (b0hi,b1hi,b0lo,b1lo)
__device__ float4 g_bfrag[16 * 16 * 32];

__device__ __forceinline__ float tf32_hi(float x) {
    return __uint_as_float(__float_as_uint(x) & 0xFFFFE000u);
}

__device__ __forceinline__ void mma_tf32(float* d, unsigned a0, unsigned a1,
                                         unsigned a2, unsigned a3,
                                         unsigned b0, unsigned b1) {
    asm volatile(
        "mma.sync.aligned.m16n8k8.row.col.f32.tf32.tf32.f32 "
        "{%0,%1,%2,%3}, {%4,%5,%6,%7}, {%8,%9}, {%0,%1,%2,%3};\n"
        : "+f"(d[0]), "+f"(d[1]), "+f"(d[2]), "+f"(d[3])
        : "r"(a0), "r"(a1), "r"(a2), "r"(a3), "r"(b0), "r"(b1));
}

// ---------------------------------------------------------------------------
// 0) Pre-swizzle fc_w (128x128) into mma.m16n8k8 B-fragment order with hi/lo
//    tf32 split.
// ---------------------------------------------------------------------------
__global__ void bprep_kernel(const float* __restrict__ fc_w) {
    int i = blockIdx.x * blockDim.x + threadIdx.x;
    if (i >= 16 * 16 * 32) return;
    int lane = i & 31;
    int nt = (i >> 5) & 15;
    int ks = i >> 9;
    int k = ks * 8 + (lane & 3);       // threadID_in_group -> k row
    int n = nt * 8 + (lane >> 2);      // groupID -> n col
    float b0 = fc_w[k * FDIM + n];
    float b1 = fc_w[(k + 4) * FDIM + n];
    float b0h = tf32_hi(b0), b1h = tf32_hi(b1);
    g_bfrag[i] = make_float4(b0h, b1h, b0 - b0h, b1 - b1h);
}

// ---------------------------------------------------------------------------
// 1) flags + hist fused (independent target arrays, no ordering needed)
// ---------------------------------------------------------------------------
__global__ void flagshist_kernel(const int* __restrict__ neg_idx, int e_neg,
                                 const int* __restrict__ edge_dst) {
    int i = blockIdx.x * blockDim.x + threadIdx.x;
    if (i < E_TOT / 4) {
        int4 d = ((const int4*)edge_dst)[i];
        atomicAdd(&g_counts[d.x - N_SRC], 1);
        atomicAdd(&g_counts[d.y - N_SRC], 1);
        atomicAdd(&g_counts[d.z - N_SRC], 1);
        atomicAdd(&g_counts[d.w - N_SRC], 1);
    }
    if (i < e_neg) g_flags[neg_idx[i]] = 1;
}

// ---------------------------------------------------------------------------
// 2) Exclusive scan: single block, 1024 threads, 20 elems/thread, 2 barriers.
//    Restores g_counts to zero for the next replay.
// ---------------------------------------------------------------------------
__global__ void scan_kernel() {
    const int PER = 20;  // 1024*20 = 20480 >= N_DST
    __shared__ int ws[32];
    const int t = threadIdx.x;
    const int lane = t & 31, wid = t >> 5;
    const int base = t * PER;

    int loc[PER];
    int s = 0;
    #pragma unroll
    for (int j = 0; j < PER; j++) {
        int idx = base + j;
        int v = (idx < N_DST) ? g_counts[idx] : 0;
        loc[j] = s;
        s += v;
    }
    int inc = s;
    #pragma unroll
    for (int off = 1; off < 32; off <<= 1) {
        int v = __shfl_up_sync(0xffffffffu, inc, off);
        if (lane >= off) inc += v;
    }
    if (lane == 31) ws[wid] = inc;
    __syncthreads();
    if (wid == 0) {
        int v = ws[lane];
        int winc = v;
        #pragma unroll
        for (int off = 1; off < 32; off <<= 1) {
            int u = __shfl_up_sync(0xffffffffu, winc, off);
            if (lane >= off) winc += u;
        }
        ws[lane] = winc - v;  // exclusive warp offset
    }
    __syncthreads();
    int off = ws[wid] + inc - s;  // exclusive thread offset
    #pragma unroll
    for (int j = 0; j < PER; j++) {
        int idx = base + j;
        if (idx < N_DST) {
            int e = off + loc[j];
            g_rowptr[idx] = e;
            g_cursor[idx] = e;
            g_counts[idx] = 0;   // restore invariant for next replay
        }
    }
    if (t == 1023) g_rowptr[N_DST] = off + s;
}

// ---------------------------------------------------------------------------
// 3) z = feat @ fc_w via tf32 tensor cores, 3xTF32 split; el/er fused into
//    the epilogue. One warp = 16 rows x 64 cols (half of N) -> 32 acc regs,
//    ~70 regs total, 3 blocks/SM instead of 2 (latency hiding).
// ---------------------------------------------------------------------------
__global__ void __launch_bounds__(256) gemm_kernel(const float* __restrict__ feat,
                                                   const float* __restrict__ attn_l,
                                                   const float* __restrict__ attn_r) {
    const int gw = (blockIdx.x * blockDim.x + threadIdx.x) >> 5;  // 0..4999
    const int row0 = (gw >> 1) * 16;
    const int ct = gw & 1;             // column half: cols [64*ct, 64*ct+64)
    if (row0 >= N_NODES) return;
    const int lane = threadIdx.x & 31;
    const int g = lane >> 2;       // groupID (row within tile)
    const int tg = lane & 3;       // threadID_in_group

    const float* ar0 = feat + (size_t)(row0 + g) * FDIM;
    const float* ar1 = ar0 + 8 * FDIM;

    float acc[8][4];
    #pragma unroll
    for (int nt = 0; nt < 8; nt++) {
        acc[nt][0] = 0.f; acc[nt][1] = 0.f; acc[nt][2] = 0.f; acc[nt][3] = 0.f;
    }

    #pragma unroll 1
    for (int ks = 0; ks < 16; ks++) {
        float a0 = ar0[ks * 8 + tg];
        float a1 = ar1[ks * 8 + tg];
        float a2 = ar0[ks * 8 + tg + 4];
        float a3 = ar1[ks * 8 + tg + 4];
        unsigned h0 = __float_as_uint(a0) & 0xFFFFE000u;
        unsigned h1 = __float_as_uint(a1) & 0xFFFFE000u;
        unsigned h2 = __float_as_uint(a2) & 0xFFFFE000u;
        unsigned h3 = __float_as_uint(a3) & 0xFFFFE000u;
        unsigned l0 = __float_as_uint(a0 - __uint_as_float(h0));
        unsigned l1 = __float_as_uint(a1 - __uint_as_float(h1));
        unsigned l2 = __float_as_uint(a2 - __uint_as_float(h2));
        unsigned l3 = __float_as_uint(a3 - __uint_as_float(h3));

        const float4* bp = g_bfrag + ks * 16 * 32 + (ct * 8) * 32 + lane;
        #pragma unroll
        for (int nt = 0; nt < 8; nt++) {
            float4 b = bp[nt * 32];
            unsigned bx = __float_as_uint(b.x), by = __float_as_uint(b.y);
            unsigned bz = __float_as_uint(b.z), bw = __float_as_uint(b.w);
            mma_tf32(acc[nt], h0, h1, h2, h3, bx, by);   // hi * hi
            mma_tf32(acc[nt], l0, l1, l2, l3, bx, by);   // lo * hi
            mma_tf32(acc[nt], h0, h1, h2, h3, bz, bw);   // hi * lo
        }
    }

    // store z (this warp's column half)
    float* zr0 = g_z + (size_t)(row0 + g) * FDIM + ct * 64;
    float* zr1 = zr0 + 8 * FDIM;
    #pragma unroll
    for (int nt = 0; nt < 8; nt++) {
        *(float2*)(zr0 + nt * 8 + tg * 2) = make_float2(acc[nt][0], acc[nt][1]);
        *(float2*)(zr1 + nt * 8 + tg * 2) = make_float2(acc[nt][2], acc[nt][3]);
    }

    // fused el/er epilogue: this half holds heads h = ct*4 + hh, hh=0..3
    // (head h uses global cols [16h,16h+16) = local ntiles {2hh, 2hh+1}).
    const int rA = (row0 + g) * NHEAD;
    const int rB = (row0 + g + 8) * NHEAD;
    #pragma unroll
    for (int hh = 0; hh < 4; hh++) {
        const int h = ct * 4 + hh;
        const int nt0 = 2 * hh, nt1 = 2 * hh + 1;
        const float* alp = attn_l + h * HDIM + tg * 2;
        const float* arp = attn_r + h * HDIM + tg * 2;
        float2 al0 = *(const float2*)(alp);
        float2 al1 = *(const float2*)(alp + 8);
        float2 arr0 = *(const float2*)(arp);
        float2 arr1 = *(const float2*)(arp + 8);
        float elA = acc[nt0][0] * al0.x + acc[nt0][1] * al0.y
                  + acc[nt1][0] * al1.x + acc[nt1][1] * al1.y;
        float elB = acc[nt0][2] * al0.x + acc[nt0][3] * al0.y
                  + acc[nt1][2] * al1.x + acc[nt1][3] * al1.y;
        float erA = acc[nt0][0] * arr0.x + acc[nt0][1] * arr0.y
                  + acc[nt1][0] * arr1.x + acc[nt1][1] * arr1.y;
        float erB = acc[nt0][2] * arr0.x + acc[nt0][3] * arr0.y
                  + acc[nt1][2] * arr1.x + acc[nt1][3] * arr1.y;
        elA += __shfl_xor_sync(0xffffffffu, elA, 1);
        elA += __shfl_xor_sync(0xffffffffu, elA, 2);
        elB += __shfl_xor_sync(0xffffffffu, elB, 1);
        elB += __shfl_xor_sync(0xffffffffu, elB, 2);
        erA += __shfl_xor_sync(0xffffffffu, erA, 1);
        erA += __shfl_xor_sync(0xffffffffu, erA, 2);
        erB += __shfl_xor_sync(0xffffffffu, erB, 1);
        erB += __shfl_xor_sync(0xffffffffu, erB, 2);
        if (tg == 0) {
            g_el[rA + h] = elA;
            g_el[rB + h] = elB;
            g_er[rA + h] = erA;
            g_er[rB + h] = erB;
        }
    }
}

// ---------------------------------------------------------------------------
// 4) Scatter edges into CSR; restores g_flags to zero after reading.
// ---------------------------------------------------------------------------
__global__ void scatter_kernel(const int* __restrict__ edge_src,
                               const int* __restrict__ edge_dst) {
    int i = blockIdx.x * blockDim.x + threadIdx.x;
    if (i >= E_TOT / 4) return;
    int4 sv = ((const int4*)edge_src)[i];
    int4 dv = ((const int4*)edge_dst)[i];
    int fl = ((const int*)g_flags)[i];
    ((int*)g_flags)[i] = 0;              // restore invariant for next replay
    int p0 = atomicAdd(&g_cursor[dv.x - N_SRC], 1);
    g_packed[p0] = sv.x | ((fl & 1) << 31);
    int p1 = atomicAdd(&g_cursor[dv.y - N_SRC], 1);
    g_packed[p1] = sv.y | (((fl >> 8) & 1) << 31);
    int p2 = atomicAdd(&g_cursor[dv.z - N_SRC], 1);
    g_packed[p2] = sv.z | (((fl >> 16) & 1) << 31);
    int p3 = atomicAdd(&g_cursor[dv.w - N_SRC], 1);
    g_packed[p3] = sv.w | (((fl >> 24) & 1) << 31);
}

// ---------------------------------------------------------------------------
// 5) Aggregation: one warp per dst node, fused pos+neg, shift-softmax,
//    4-deep software pipeline (statically-indexed stages -> MLP=4 on the
//    z gathers), per-node loss fused (atomicAdd to g_loss).
// ---------------------------------------------------------------------------
#define AGG_LOAD(J, IDX)                                                     \
    {                                                                        \
        int _i = (IDX);                                                      \
        if (_i < pend) {                                                     \
            unsigned _u = (unsigned)g_packed[_i];                            \
            u##J = _u;                                                       \
            int _s = (int)(_u & 0x7fffffffu);                                \
            el##J = g_el[_s * NHEAD + h];                                    \
            z##J = *(const float4*)(g_z + (size_t)_s * FDIM + lane * 4);     \
        }                                                                    \
    }

#define AGG_PROC(J, IDX)                                                     \
    if ((IDX) < pend) {                                                      \
        float _e = el##J + er_h;                                             \
        _e = (_e >= 0.f) ? _e : NEG_SLOPE * _e;                              \
        float _w = __expf(_e - E_SHIFT);                                     \
        dP += _w;                                                            \
        aP.x += _w * z##J.x; aP.y += _w * z##J.y;                            \
        aP.z += _w * z##J.z; aP.w += _w * z##J.w;                            \
        if (u##J >> 31) {                                                    \
            dN += _w;                                                        \
            aN.x += _w * z##J.x; aN.y += _w * z##J.y;                        \
            aN.z += _w * z##J.z; aN.w += _w * z##J.w;                        \
        }                                                                    \
    }

__global__ void aggregate_kernel(const float* __restrict__ bias,
                                 const float* __restrict__ prelu_a,
                                 float* __restrict__ out_pos) {
    const int warp = (blockIdx.x * blockDim.x + threadIdx.x) >> 5;
    if (warp >= N_DST) return;
    const int lane = threadIdx.x & 31;
    const int i = warp;
    const int n = N_SRC + i;
    const int h = lane >> 2;

    const float er_h = g_er[n * NHEAD + h];
    float4 zself = *(const float4*)(g_z + (size_t)n * FDIM + lane * 4);
    float e_self = g_el[n * NHEAD + h] + er_h;
    e_self = (e_self >= 0.f) ? e_self : NEG_SLOPE * e_self;
    float ws = __expf(e_self - E_SHIFT);

    float dP = ws, dN = ws;
    float4 aP = make_float4(ws * zself.x, ws * zself.y, ws * zself.z, ws * zself.w);
    float4 aN = aP;

    const int pbeg = g_rowptr[i], pend = g_rowptr[i + 1];

    unsigned u0 = 0, u1 = 0, u2 = 0, u3 = 0;
    float el0 = 0.f, el1 = 0.f, el2 = 0.f, el3 = 0.f;
    float4 z0 = {}, z1 = {}, z2 = {}, z3 = {};

    AGG_LOAD(0, pbeg + 0);
    AGG_LOAD(1, pbeg + 1);
    AGG_LOAD(2, pbeg + 2);
    AGG_LOAD(3, pbeg + 3);

    #pragma unroll 1
    for (int k = pbeg; k < pend; k += 4) {
        AGG_PROC(0, k + 0); AGG_LOAD(0, k + 4);
        AGG_PROC(1, k + 1); AGG_LOAD(1, k + 5);
        AGG_PROC(2, k + 2); AGG_LOAD(2, k + 6);
        AGG_PROC(3, k + 3); AGG_LOAD(3, k + 7);
    }

    const float pa = prelu_a[0];
    const int f0 = lane * 4;
    float b0 = bias[f0], b1 = bias[f0 + 1], b2 = bias[f0 + 2], b3 = bias[f0 + 3];

    float pv0, pv1, pv2, pv3, nv0, nv1, nv2, nv3;
    {   // positive
        float inv = 1.f / dP;
        float v0 = aP.x * inv + b0; v0 = (v0 >= 0.f) ? v0 : pa * v0;
        float v1 = aP.y * inv + b1; v1 = (v1 >= 0.f) ? v1 : pa * v1;
        float v2 = aP.z * inv + b2; v2 = (v2 >= 0.f) ? v2 : pa * v2;
        float v3 = aP.w * inv + b3; v3 = (v3 >= 0.f) ? v3 : pa * v3;
        #pragma unroll
        for (int off = 4; off <= 16; off <<= 1) {
            v0 += __shfl_xor_sync(0xffffffffu, v0, off);
            v1 += __shfl_xor_sync(0xffffffffu, v1, off);
            v2 += __shfl_xor_sync(0xffffffffu, v2, off);
            v3 += __shfl_xor_sync(0xffffffffu, v3, off);
        }
        pv0 = v0 * 0.125f; pv1 = v1 * 0.125f; pv2 = v2 * 0.125f; pv3 = v3 * 0.125f;
        if (lane < 4) {
            float* o = out_pos + (size_t)i * HDIM + lane * 4;
            o[0] = pv0; o[1] = pv1; o[2] = pv2; o[3] = pv3;
        }
    }
    {   // negative
        float inv = 1.f / dN;
        float v0 = aN.x * inv + b0; v0 = (v0 >= 0.f) ? v0 : pa * v0;
        float v1 = aN.y * inv + b1; v1 = (v1 >= 0.f) ? v1 : pa * v1;
        float v2 = aN.z * inv + b2; v2 = (v2 >= 0.f) ? v2 : pa * v2;
        float v3 = aN.w * inv + b3; v3 = (v3 >= 0.f) ? v3 : pa * v3;
        #pragma unroll
        for (int off = 4; off <= 16; off <<= 1) {
            v0 += __shfl_xor_sync(0xffffffffu, v0, off);
            v1 += __shfl_xor_sync(0xffffffffu, v1, off);
            v2 += __shfl_xor_sync(0xffffffffu, v2, off);
            v3 += __shfl_xor_sync(0xffffffffu, v3, off);
        }
        nv0 = v0 * 0.125f; nv1 = v1 * 0.125f; nv2 = v2 * 0.125f; nv3 = v3 * 0.125f;
    }

    // fused loss contribution
    float dot = pv0 * nv0 + pv1 * nv1 + pv2 * nv2 + pv3 * nv3;
    float na  = pv0 * pv0 + pv1 * pv1 + pv2 * pv2 + pv3 * pv3;
    float nb  = nv0 * nv0 + nv1 * nv1 + nv2 * nv2 + nv3 * nv3;
    dot += __shfl_xor_sync(0xffffffffu, dot, 1);
    dot += __shfl_xor_sync(0xffffffffu, dot, 2);
    na  += __shfl_xor_sync(0xffffffffu, na, 1);
    na  += __shfl_xor_sync(0xffffffffu, na, 2);
    nb  += __shfl_xor_sync(0xffffffffu, nb, 1);
    nb  += __shfl_xor_sync(0xffffffffu, nb, 2);
    if (lane == 0) {
        float den = fmaxf(sqrtf(na), 1e-8f) * fmaxf(sqrtf(nb), 1e-8f);
        atomicAdd(&g_loss, __expf(dot / den / TEM));
    }
}

// ---------------------------------------------------------------------------
// 6) finalize: out[0] = log(sum); reset accumulator for the next replay.
// ---------------------------------------------------------------------------
__global__ void finalize_kernel(float* __restrict__ out) {
    out[0] = logf(g_loss);
    g_loss = 0.f;
}

// ---------------------------------------------------------------------------
extern "C" void kernel_launch(void* const* d_in, const int* in_sizes, int n_in,
                              void* d_out, int out_size) {
    const float* feat    = (const float*)d_in[0];
    const float* fc_w    = (const float*)d_in[1];
    const float* attn_l  = (const float*)d_in[2];
    const float* attn_r  = (const float*)d_in[3];
    const float* bias    = (const float*)d_in[4];
    const float* prelu_a = (const float*)d_in[5];
    const int*   edge_src = (const int*)d_in[6];
    const int*   edge_dst = (const int*)d_in[7];
    const int*   neg_idx  = (const int*)d_in[8];
    const int    e_neg = in_sizes[8];

    float* out = (float*)d_out;          // [0] = loss, [1..] = h_pos (N_DST x 16)
    float* out_pos = out + 1;

    int fh_n = (e_neg > E_TOT / 4) ? e_neg : (E_TOT / 4);

    bprep_kernel<<<32, 256>>>(fc_w);                                          // 0
    flagshist_kernel<<<(fh_n + 255) / 256, 256>>>(neg_idx, e_neg, edge_dst);  // 1
    scan_kernel<<<1, 1024>>>();                                               // 2
    gemm_kernel<<<(N_NODES / 16 * 2 * 32 + 255) / 256, 256>>>(feat, attn_l, attn_r); // 3 (profiled)
    scatter_kernel<<<(E_TOT / 4 + 255) / 256, 256>>>(edge_src, edge_dst);     // 4
    aggregate_kernel<<<(N_DST + 7) / 8, 256>>>(bias, prelu_a, out_pos);       // 5
    finalize_kernel<<<1, 1>>>(out);                                           // 6
}